// round 9
// baseline (speedup 1.0000x reference)
#include <cuda_runtime.h>
#include <math.h>
#include <stdint.h>

// ---------------------------------------------------------------------------
// Static device scratch (no allocations allowed anywhere).
// Sized for N <= 65536 nodes, E_total <= 2.2M edges (instance: 50000 / 850000).
// ---------------------------------------------------------------------------
#define NMAX 65536
#define EMAX 2200000

__device__ float g_h1[(size_t)NMAX * 256];   // layer-1 features  h1 = x @ W1
__device__ float g_x2[(size_t)NMAX * 256];   // relu(agg1 + b1) = layer-2 input
__device__ float g_h2[(size_t)NMAX * 64];    // layer-2 features  h2 = x2 @ W2
__device__ float g_as1[NMAX * 4];
__device__ float g_ad1[NMAX * 4];
__device__ float g_as2[NMAX];
__device__ float g_ad2[NMAX];
__device__ int   g_deg[NMAX];
__device__ int   g_pos[NMAX];
__device__ int   g_rowptr[NMAX + 1];
__device__ int   g_esrc[EMAX];               // src node of each dst-sorted edge

// ---------------------------------------------------------------------------
// CSR construction (counting sort by destination). edge_index is INT32.
// ---------------------------------------------------------------------------
__global__ void zero_deg_kernel(int Nn) {
    int i = blockIdx.x * blockDim.x + threadIdx.x;
    if (i < Nn) g_deg[i] = 0;
}

__global__ void count_kernel(const int* __restrict__ ei, int E, int Nn) {
    int i = blockIdx.x * blockDim.x + threadIdx.x;
    int tot = E + Nn;
    if (i >= tot) return;
    int d = (i < E) ? ei[E + i] : (i - E);
    if ((unsigned)d < (unsigned)Nn) atomicAdd(&g_deg[d], 1);
}

__global__ void scan_kernel(int N) {
    __shared__ int ssum[1024];
    int tid = threadIdx.x;
    int chunk = (N + 1023) >> 10;
    int start = tid * chunk;
    int end = min(start + chunk, N);
    int s = 0;
    for (int i = start; i < end; i++) s += g_deg[i];
    ssum[tid] = s;
    __syncthreads();
    for (int off = 1; off < 1024; off <<= 1) {
        int v = (tid >= off) ? ssum[tid - off] : 0;
        __syncthreads();
        ssum[tid] += v;
        __syncthreads();
    }
    int run = (tid > 0) ? ssum[tid - 1] : 0;
    for (int i = start; i < end; i++) {
        g_rowptr[i] = run;
        g_pos[i] = run;
        run += g_deg[i];
    }
    if (start < N && end == N) g_rowptr[N] = run;
}

__global__ void fill_kernel(const int* __restrict__ ei, int E, int Nn) {
    int i = blockIdx.x * blockDim.x + threadIdx.x;
    int tot = E + Nn;
    if (i >= tot) return;
    int s, d;
    if (i < E) { s = ei[i]; d = ei[E + i]; }
    else       { s = d = i - E; }
    if ((unsigned)d >= (unsigned)Nn || (unsigned)s >= (unsigned)Nn) return;
    int slot = atomicAdd(&g_pos[d], 1);
    g_esrc[slot] = s;
}

// ---------------------------------------------------------------------------
// Tensor-core GEMM via mma.sync.m16n8k8 tf32 with 3-term split for full fp32
// accuracy: x = hi + lo (both rna-rounded tf32);  x*y ~= hi*hi + hi*lo + lo*hi.
// C[M,N] = A[M,K] @ B[K,N], row-major. 256 threads = 8 warps (4x2 warp grid).
// Requires N % BN == 0, K % BK == 0 (true here).
// ---------------------------------------------------------------------------
__device__ __forceinline__ float f2tf32(float x) {
    uint32_t u;
    asm("cvt.rna.tf32.f32 %0, %1;" : "=r"(u) : "f"(x));
    return __uint_as_float(u);
}

__device__ __forceinline__ void mma_tf32(float c[4], const uint32_t a[4],
                                         const uint32_t b[2]) {
    asm volatile(
        "mma.sync.aligned.m16n8k8.row.col.f32.tf32.tf32.f32 "
        "{%0,%1,%2,%3}, {%4,%5,%6,%7}, {%8,%9}, {%0,%1,%2,%3};\n"
        : "+f"(c[0]), "+f"(c[1]), "+f"(c[2]), "+f"(c[3])
        : "r"(a[0]), "r"(a[1]), "r"(a[2]), "r"(a[3]), "r"(b[0]), "r"(b[1]));
}

template <int BM, int BN, int BK, int WM, int WN>
__device__ __forceinline__ void mma_gemm_body(const float* __restrict__ A,
                                              const float* __restrict__ B,
                                              float* __restrict__ C,
                                              int M, int N, int K) {
    constexpr int THREADS = 256;
    constexpr int MT = WM / 16;                     // m-tiles per warp
    constexpr int NT = WN / 8;                      // n-tiles per warp
    constexpr int A_F4 = BM * BK / 4 / THREADS;     // float4 loads per thread
    constexpr int B_F4 = BK * BN / 4 / THREADS;
    constexpr int APAD = BK + 1;
    constexpr int BPAD = BN + 4;

    __shared__ float Ah[BM][APAD], Al[BM][APAD];
    __shared__ float Bh[BK][BPAD], Bl[BK][BPAD];

    const int tid    = threadIdx.x;
    const int warpId = tid >> 5;
    const int lane   = tid & 31;
    const int g = lane >> 2;                        // group id 0..7
    const int t = lane & 3;                         // thread-in-group 0..3

    const int row0 = blockIdx.y * BM;
    const int col0 = blockIdx.x * BN;
    const int wm0  = (warpId & 3) * WM;
    const int wn0  = (warpId >> 2) * WN;

    float4 aReg[A_F4], bReg[B_F4];

    auto fetch = [&](int k0) {
#pragma unroll
        for (int q = 0; q < A_F4; q++) {
            int i = tid + q * THREADS;
            int r = i / (BK / 4);
            int c = (i % (BK / 4)) * 4;
            aReg[q] = make_float4(0.f, 0.f, 0.f, 0.f);
            if (row0 + r < M)
                aReg[q] = *reinterpret_cast<const float4*>(
                    A + (size_t)(row0 + r) * K + k0 + c);
        }
#pragma unroll
        for (int q = 0; q < B_F4; q++) {
            int i = tid + q * THREADS;
            int r = i / (BN / 4);
            int c = (i % (BN / 4)) * 4;
            bReg[q] = *reinterpret_cast<const float4*>(
                B + (size_t)(k0 + r) * N + col0 + c);
        }
    };
    auto stage = [&]() {
#pragma unroll
        for (int q = 0; q < A_F4; q++) {
            int i = tid + q * THREADS;
            int r = i / (BK / 4);
            int c = (i % (BK / 4)) * 4;
            float v[4] = {aReg[q].x, aReg[q].y, aReg[q].z, aReg[q].w};
#pragma unroll
            for (int e = 0; e < 4; e++) {
                float hi = f2tf32(v[e]);
                Ah[r][c + e] = hi;
                Al[r][c + e] = f2tf32(v[e] - hi);
            }
        }
#pragma unroll
        for (int q = 0; q < B_F4; q++) {
            int i = tid + q * THREADS;
            int r = i / (BN / 4);
            int c = (i % (BN / 4)) * 4;
            float v[4] = {bReg[q].x, bReg[q].y, bReg[q].z, bReg[q].w};
#pragma unroll
            for (int e = 0; e < 4; e++) {
                float hi = f2tf32(v[e]);
                Bh[r][c + e] = hi;
                Bl[r][c + e] = f2tf32(v[e] - hi);
            }
        }
    };

    float acc[MT][NT][4];
#pragma unroll
    for (int mt = 0; mt < MT; mt++)
#pragma unroll
        for (int nt = 0; nt < NT; nt++)
#pragma unroll
            for (int e = 0; e < 4; e++) acc[mt][nt][e] = 0.f;

    fetch(0);
    stage();
    __syncthreads();

    for (int k0 = 0; k0 < K; k0 += BK) {
        if (k0 + BK < K) fetch(k0 + BK);   // prefetch next tile into registers

#pragma unroll
        for (int ks = 0; ks < BK; ks += 8) {
            uint32_t ah[MT][4], al[MT][4];
#pragma unroll
            for (int mt = 0; mt < MT; mt++) {
                int r = wm0 + mt * 16 + g;
                ah[mt][0] = __float_as_uint(Ah[r    ][ks + t    ]);
                ah[mt][1] = __float_as_uint(Ah[r + 8][ks + t    ]);
                ah[mt][2] = __float_as_uint(Ah[r    ][ks + t + 4]);
                ah[mt][3] = __float_as_uint(Ah[r + 8][ks + t + 4]);
                al[mt][0] = __float_as_uint(Al[r    ][ks + t    ]);
                al[mt][1] = __float_as_uint(Al[r + 8][ks + t    ]);
                al[mt][2] = __float_as_uint(Al[r    ][ks + t + 4]);
                al[mt][3] = __float_as_uint(Al[r + 8][ks + t + 4]);
            }
            uint32_t bh[NT][2], bl[NT][2];
#pragma unroll
            for (int nt = 0; nt < NT; nt++) {
                int c = wn0 + nt * 8 + g;
                bh[nt][0] = __float_as_uint(Bh[ks + t    ][c]);
                bh[nt][1] = __float_as_uint(Bh[ks + t + 4][c]);
                bl[nt][0] = __float_as_uint(Bl[ks + t    ][c]);
                bl[nt][1] = __float_as_uint(Bl[ks + t + 4][c]);
            }
#pragma unroll
            for (int mt = 0; mt < MT; mt++)
#pragma unroll
                for (int nt = 0; nt < NT; nt++) {
                    mma_tf32(acc[mt][nt], ah[mt], bh[nt]);   // hi*hi
                    mma_tf32(acc[mt][nt], ah[mt], bl[nt]);   // hi*lo
                    mma_tf32(acc[mt][nt], al[mt], bh[nt]);   // lo*hi
                }
        }
        __syncthreads();
        if (k0 + BK < K) {
            stage();
            __syncthreads();
        }
    }

    // ---- epilogue: c0/c1 at (r, c..c+1), c2/c3 at (r+8, c..c+1) ----
#pragma unroll
    for (int mt = 0; mt < MT; mt++)
#pragma unroll
        for (int nt = 0; nt < NT; nt++) {
            int r = row0 + wm0 + mt * 16 + g;
            int c = col0 + wn0 + nt * 8 + 2 * t;
            if (r < M)
                *reinterpret_cast<float2*>(C + (size_t)r * N + c) =
                    make_float2(acc[mt][nt][0], acc[mt][nt][1]);
            if (r + 8 < M)
                *reinterpret_cast<float2*>(C + (size_t)(r + 8) * N + c) =
                    make_float2(acc[mt][nt][2], acc[mt][nt][3]);
        }
}

__global__ void __launch_bounds__(256)
sgemm1_kernel(const float* __restrict__ A, const float* __restrict__ B,
              int M, int N, int K) {
    mma_gemm_body<128, 128, 16, 32, 64>(A, B, g_h1, M, N, K);
}

__global__ void __launch_bounds__(256)
sgemm2_kernel(const float* __restrict__ B, int M, int N, int K) {
    mma_gemm_body<128, 64, 16, 32, 32>(g_x2, B, g_h2, M, N, K);
}

// ---------------------------------------------------------------------------
// alpha_s[n,h] = <h[n,h,:], a_src[h,:]>,  alpha_d likewise.  One warp / node.
// ---------------------------------------------------------------------------
template <int H, int C>
__device__ __forceinline__ void alpha_body(const float* __restrict__ hfeat,
                                           const float* __restrict__ a_src,
                                           const float* __restrict__ a_dst,
                                           float* __restrict__ as_out,
                                           float* __restrict__ ad_out, int Nn) {
    constexpr int HC  = H * C;
    constexpr int CPL = HC / 32;   // channels per lane
    constexpr int LPH = 32 / H;    // lanes per head
    int warp = (blockIdx.x * blockDim.x + threadIdx.x) >> 5;
    int lane = threadIdx.x & 31;
    if (warp >= Nn) return;

    const float* hp = hfeat + (size_t)warp * HC + lane * CPL;
    float ss = 0.f, sd = 0.f;
#pragma unroll
    for (int k = 0; k < CPL; k++) {
        float v = hp[k];
        ss = fmaf(v, a_src[lane * CPL + k], ss);
        sd = fmaf(v, a_dst[lane * CPL + k], sd);
    }
#pragma unroll
    for (int o = LPH / 2; o > 0; o >>= 1) {
        ss += __shfl_xor_sync(0xFFFFFFFFu, ss, o);
        sd += __shfl_xor_sync(0xFFFFFFFFu, sd, o);
    }
    if ((lane % LPH) == 0) {
        int head = lane / LPH;
        as_out[warp * H + head] = ss;
        ad_out[warp * H + head] = sd;
    }
}

__global__ void alpha1_kernel(const float* __restrict__ a_src,
                              const float* __restrict__ a_dst, int Nn) {
    alpha_body<4, 64>(g_h1, a_src, a_dst, g_as1, g_ad1, Nn);
}

__global__ void alpha2_kernel(const float* __restrict__ a_src,
                              const float* __restrict__ a_dst, int Nn) {
    alpha_body<1, 64>(g_h2, a_src, a_dst, g_as2, g_ad2, Nn);
}

// ---------------------------------------------------------------------------
// Per-node edge softmax + weighted aggregation.  One warp per destination.
// Max-free softmax: e = leaky_relu(as[src]+ad[dst]) is bounded (|e| ~< 10),
// so exp(e)/sum(exp(e)) is overflow-safe and mathematically identical.
// ---------------------------------------------------------------------------
template <int H, int C, bool RELU>
__device__ __forceinline__ void aggregate_body(const float* __restrict__ hfeat,
                                               const float* __restrict__ as_in,
                                               const float* __restrict__ ad_in,
                                               const float* __restrict__ bias,
                                               float* __restrict__ out, int Nn) {
    constexpr int HC  = H * C;
    constexpr int CPL = HC / 32;     // 8 (layer1) or 2 (layer2)
    int warp = (blockIdx.x * blockDim.x + threadIdx.x) >> 5;
    int lane = threadIdx.x & 31;
    if (warp >= Nn) return;
    const int n   = warp;
    const int beg = g_rowptr[n];
    const int end = g_rowptr[n + 1];

    float adv[H];
#pragma unroll
    for (int h = 0; h < H; h++) adv[h] = ad_in[n * H + h];

    // ---- phase 1: per-head exp-sum over incoming edges ----
    float sm[H];
#pragma unroll
    for (int h = 0; h < H; h++) sm[h] = 0.f;
    for (int j = beg + lane; j < end; j += 32) {
        int s = g_esrc[j];
        if constexpr (H == 4) {
            float4 av = *reinterpret_cast<const float4*>(as_in + s * 4);
            float ev[4] = {av.x, av.y, av.z, av.w};
#pragma unroll
            for (int h = 0; h < 4; h++) {
                float e = ev[h] + adv[h];
                e = (e > 0.f) ? e : 0.2f * e;      // leaky_relu(0.2)
                sm[h] += expf(e);
            }
        } else {
            float e = as_in[s] + adv[0];
            e = (e > 0.f) ? e : 0.2f * e;
            sm[0] += expf(e);
        }
    }
#pragma unroll
    for (int h = 0; h < H; h++) {
#pragma unroll
        for (int o = 16; o > 0; o >>= 1)
            sm[h] += __shfl_xor_sync(0xFFFFFFFFu, sm[h], o);
        sm[h] = 1.0f / (sm[h] + 1e-16f);           // inverse denom
    }

    // ---- phase 2: weighted gather of h[src]; whole warp covers HC channels
    //      per edge; 4 edges in flight for memory-level parallelism.
    const int chan0 = lane * CPL;
    const int headL = chan0 / C;
    const float adh  = adv[headL];
    const float ismh = sm[headL];

    auto edge_alpha = [&](int s) -> float {
        float e = as_in[s * H + headL] + adh;
        e = (e > 0.f) ? e : 0.2f * e;
        return expf(e) * ismh;
    };

    float acc[CPL];
#pragma unroll
    for (int k = 0; k < CPL; k++) acc[k] = 0.f;

    int j = beg;
    for (; j + 3 < end; j += 4) {
        int   s[4];
        float a[4];
#pragma unroll
        for (int q = 0; q < 4; q++) s[q] = g_esrc[j + q];
#pragma unroll
        for (int q = 0; q < 4; q++) a[q] = edge_alpha(s[q]);
        if constexpr (CPL == 8) {
            float4 va[4], vb[4];
#pragma unroll
            for (int q = 0; q < 4; q++) {
                const float* p = hfeat + (size_t)s[q] * HC + chan0;
                va[q] = *reinterpret_cast<const float4*>(p);
                vb[q] = *reinterpret_cast<const float4*>(p + 4);
            }
#pragma unroll
            for (int q = 0; q < 4; q++) {
                acc[0] = fmaf(va[q].x, a[q], acc[0]);
                acc[1] = fmaf(va[q].y, a[q], acc[1]);
                acc[2] = fmaf(va[q].z, a[q], acc[2]);
                acc[3] = fmaf(va[q].w, a[q], acc[3]);
                acc[4] = fmaf(vb[q].x, a[q], acc[4]);
                acc[5] = fmaf(vb[q].y, a[q], acc[5]);
                acc[6] = fmaf(vb[q].z, a[q], acc[6]);
                acc[7] = fmaf(vb[q].w, a[q], acc[7]);
            }
        } else {
            float2 v[4];
#pragma unroll
            for (int q = 0; q < 4; q++)
                v[q] = *reinterpret_cast<const float2*>(hfeat + (size_t)s[q] * HC + chan0);
#pragma unroll
            for (int q = 0; q < 4; q++) {
                acc[0] = fmaf(v[q].x, a[q], acc[0]);
                acc[1] = fmaf(v[q].y, a[q], acc[1]);
            }
        }
    }
    for (; j < end; j++) {
        int s0 = g_esrc[j];
        float a0 = edge_alpha(s0);
        const float* p0 = hfeat + (size_t)s0 * HC + chan0;
        if constexpr (CPL == 8) {
            float4 v0a = *reinterpret_cast<const float4*>(p0);
            float4 v0b = *reinterpret_cast<const float4*>(p0 + 4);
            acc[0] = fmaf(v0a.x, a0, acc[0]); acc[1] = fmaf(v0a.y, a0, acc[1]);
            acc[2] = fmaf(v0a.z, a0, acc[2]); acc[3] = fmaf(v0a.w, a0, acc[3]);
            acc[4] = fmaf(v0b.x, a0, acc[4]); acc[5] = fmaf(v0b.y, a0, acc[5]);
            acc[6] = fmaf(v0b.z, a0, acc[6]); acc[7] = fmaf(v0b.w, a0, acc[7]);
        } else {
            float2 v0 = *reinterpret_cast<const float2*>(p0);
            acc[0] = fmaf(v0.x, a0, acc[0]); acc[1] = fmaf(v0.y, a0, acc[1]);
        }
    }

    // ---- epilogue: bias (+ optional relu), single coalesced write ----
    float* op = out + (size_t)n * HC + chan0;
#pragma unroll
    for (int k = 0; k < CPL; k++) {
        float v = acc[k] + bias[chan0 + k];
        if constexpr (RELU) v = fmaxf(v, 0.f);
        op[k] = v;
    }
}

__global__ void agg1_kernel(const float* __restrict__ bias, int Nn) {
    aggregate_body<4, 64, true>(g_h1, g_as1, g_ad1, bias, g_x2, Nn);
}

__global__ void agg2_kernel(const float* __restrict__ bias,
                            float* __restrict__ out, int Nn) {
    aggregate_body<1, 64, false>(g_h2, g_as2, g_ad2, bias, out, Nn);
}

// ---------------------------------------------------------------------------
// kernel_launch — pure kernel launches, no runtime API calls.
// inputs: x, edge_index, W1, a_src1, a_dst1, b1, W2, a_src2, a_dst2, b2
// ---------------------------------------------------------------------------
extern "C" void kernel_launch(void* const* d_in, const int* in_sizes, int n_in,
                              void* d_out, int out_size) {
    const float* x      = (const float*)d_in[0];
    const int*   ei     = (const int*)d_in[1];     // int32 (JAX x64 disabled)
    const float* W1     = (const float*)d_in[2];
    const float* a_src1 = (const float*)d_in[3];
    const float* a_dst1 = (const float*)d_in[4];
    const float* b1     = (const float*)d_in[5];
    const float* W2     = (const float*)d_in[6];
    const float* a_src2 = (const float*)d_in[7];
    const float* a_dst2 = (const float*)d_in[8];
    const float* b2     = (const float*)d_in[9];

    const int C   = in_sizes[9];            // 64
    const int H   = in_sizes[3] / C;        // 4
    const int HC1 = H * C;                  // 256
    const int Fin = in_sizes[2] / HC1;      // 128
    const int Nn  = in_sizes[0] / Fin;      // 50000
    const int E   = in_sizes[1] / 2;        // 800000
    const int Etot = E + Nn;

    if (Nn > NMAX || Etot > EMAX || H != 4 || C != 64) return;

    // ---- build dst-sorted CSR (counting sort) ----
    zero_deg_kernel<<<(Nn + 255) / 256, 256>>>(Nn);
    count_kernel<<<(Etot + 255) / 256, 256>>>(ei, E, Nn);
    scan_kernel<<<1, 1024>>>(Nn);
    fill_kernel<<<(Etot + 255) / 256, 256>>>(ei, E, Nn);

    const int warpBlocks = (Nn + 7) / 8;    // 8 warps / 256-thread block

    // ---- layer 1 ----
    {
        dim3 grid(HC1 / 128, (Nn + 127) / 128);
        sgemm1_kernel<<<grid, 256>>>(x, W1, Nn, HC1, Fin);
    }
    alpha1_kernel<<<warpBlocks, 256>>>(a_src1, a_dst1, Nn);
    agg1_kernel<<<warpBlocks, 256>>>(b1, Nn);

    // ---- layer 2 ----
    {
        dim3 grid(C / 64, (Nn + 127) / 128);
        sgemm2_kernel<<<grid, 256>>>(W2, Nn, C, HC1);
    }
    alpha2_kernel<<<warpBlocks, 256>>>(a_src2, a_dst2, Nn);
    agg2_kernel<<<warpBlocks, 256>>>(b2, (float*)d_out, Nn);
}